// round 2
// baseline (speedup 1.0000x reference)
#include <cuda_runtime.h>
#include <cstdint>

// Problem constants (B=8, M=512, A=16, F=128), cgc [16,16,16] ~25% dense.
#define AA 16
#define FF 128
#define TILE_FLOATS (AA * FF)        // 2048 floats per (b,m) tile
#define MAX_NNZ (AA * AA * AA)       // 4096 worst case
#define WARPS_PER_BLOCK 4

// Compressed sparse metadata built on-device each launch (graph-capturable,
// deterministic). Slot s = d*16 + a; per slot a list of (c*128, val).
__device__ int   g_off[257];
__device__ int   g_coff[MAX_NNZ];    // c * 128 (float offset into y tile row base)
__device__ float g_val[MAX_NNZ];

// ---------------------------------------------------------------------------
// Prep kernel: 1 block, 256 threads. Thread t handles slot (d = t>>4, a = t&15),
// scans c = 0..15 of cgc[a][d][c], prefix-sums counts, writes compressed lists.
// ---------------------------------------------------------------------------
__global__ void tp_prep_kernel(const float* __restrict__ cgc) {
    __shared__ int scan[256];
    int t = threadIdx.x;
    int d = t >> 4;
    int a = t & 15;

    float vals[AA];
    int   coffs[AA];
    int n = 0;
#pragma unroll
    for (int c = 0; c < AA; ++c) {
        float v = cgc[a * 256 + d * 16 + c];
        if (v != 0.0f) {
            vals[n]  = v;
            coffs[n] = c * FF;
            ++n;
        }
    }

    scan[t] = n;
    __syncthreads();
    // Hillis-Steele inclusive scan over 256 counts
    for (int off = 1; off < 256; off <<= 1) {
        int v = (t >= off) ? scan[t - off] : 0;
        __syncthreads();
        scan[t] += v;
        __syncthreads();
    }
    int base = scan[t] - n;   // exclusive
    g_off[t] = base;
    if (t == 255) g_off[256] = scan[255];

    for (int i = 0; i < n; ++i) {
        g_coff[base + i] = coffs[i];
        g_val[base + i]  = vals[i];
    }
}

// ---------------------------------------------------------------------------
// Main kernel: block = 128 threads = 4 warps; each warp owns one (b,m) tile.
// Lane handles 4 consecutive f (float4). x,y tiles + metadata staged in shared.
//   out[d,f] = sum_a x[a,f] * ( sum_{c in list(d,a)} val * y[c,f] )
// Accumulators and loop indices d,a are static -> registers; only c is dynamic
// and resolves through shared memory (conflict-free float4, lanes consecutive).
// ---------------------------------------------------------------------------
__global__ __launch_bounds__(128) void tp_main_kernel(
    const float* __restrict__ x,
    const float* __restrict__ y,
    float* __restrict__ out)
{
    extern __shared__ float smem[];
    float* xs   = smem;                                  // 4 * 2048 floats
    float* ys   = smem + WARPS_PER_BLOCK * TILE_FLOATS;  // 4 * 2048 floats
    int*   soff = (int*)(ys + WARPS_PER_BLOCK * TILE_FLOATS);  // 257 (+3 pad)
    int*   sc   = soff + 260;                            // 4096
    float* sv   = (float*)(sc + MAX_NNZ);                // 4096

    const int tid  = threadIdx.x;
    const int wid  = tid >> 5;
    const int lane = tid & 31;
    const int bm   = blockIdx.x * WARPS_PER_BLOCK + wid;

    // Stage this warp's x,y tiles (2048 floats each = 512 float4, 16 per lane)
    {
        const float4* xg  = (const float4*)(x + (size_t)bm * TILE_FLOATS);
        const float4* yg  = (const float4*)(y + (size_t)bm * TILE_FLOATS);
        float4* xs4 = (float4*)(xs + wid * TILE_FLOATS);
        float4* ys4 = (float4*)(ys + wid * TILE_FLOATS);
#pragma unroll
        for (int i = 0; i < TILE_FLOATS / 4; i += 32) {
            xs4[i + lane] = xg[i + lane];
            ys4[i + lane] = yg[i + lane];
        }
    }

    // Stage metadata (whole block cooperatively)
    for (int i = tid; i < 257; i += 128) soff[i] = g_off[i];
    const int nnz = g_off[256];
    for (int i = tid; i < nnz; i += 128) {
        sc[i] = g_coff[i];
        sv[i] = g_val[i];
    }
    __syncthreads();

    const float* xw = xs + wid * TILE_FLOATS;
    const float* yw = ys + wid * TILE_FLOATS;
    const int fo = lane * 4;
    float* outw = out + (size_t)bm * TILE_FLOATS + fo;

    for (int d = 0; d < AA; ++d) {
        float4 acc = make_float4(0.f, 0.f, 0.f, 0.f);
#pragma unroll
        for (int a = 0; a < AA; ++a) {
            const int slot = (d << 4) + a;
            int j       = soff[slot];
            const int e = soff[slot + 1];
            float4 s = make_float4(0.f, 0.f, 0.f, 0.f);
            for (; j < e; ++j) {
                const int   co = sc[j];
                const float v  = sv[j];
                const float4 yv = *(const float4*)(yw + co + fo);
                s.x = fmaf(v, yv.x, s.x);
                s.y = fmaf(v, yv.y, s.y);
                s.z = fmaf(v, yv.z, s.z);
                s.w = fmaf(v, yv.w, s.w);
            }
            const float4 xv = *(const float4*)(xw + (a << 7) + fo);
            acc.x = fmaf(xv.x, s.x, acc.x);
            acc.y = fmaf(xv.y, s.y, acc.y);
            acc.z = fmaf(xv.z, s.z, acc.z);
            acc.w = fmaf(xv.w, s.w, acc.w);
        }
        *(float4*)(outw + (d << 7)) = acc;
    }
}

extern "C" void kernel_launch(void* const* d_in, const int* in_sizes, int n_in,
                              void* d_out, int out_size) {
    const float* x   = (const float*)d_in[0];
    const float* y   = (const float*)d_in[1];
    const float* cgc = (const float*)d_in[2];
    float* out = (float*)d_out;

    const int n_bm = in_sizes[0] / TILE_FLOATS;          // 4096
    const int grid = n_bm / WARPS_PER_BLOCK;             // 1024

    const int smem_bytes =
        WARPS_PER_BLOCK * TILE_FLOATS * 4 * 2   // xs + ys
        + 260 * 4                               // soff (+pad)
        + MAX_NNZ * 4 * 2;                      // sc + sv

    cudaFuncSetAttribute(tp_main_kernel,
                         cudaFuncAttributeMaxDynamicSharedMemorySize,
                         smem_bytes);

    tp_prep_kernel<<<1, 256>>>(cgc);
    tp_main_kernel<<<grid, 128, smem_bytes>>>(x, y, out);
}

// round 4
// speedup vs baseline: 1.4616x; 1.4616x over previous
#include <cuda_runtime.h>
#include <cstdint>

// Problem constants: B=8, M=512, A=16, F=128; cgc [a,d,c] ~25% dense (~1024 nnz).
#define AA 16
#define FF 128
#define TILE_FLOATS (AA * FF)     // 2048 floats per (b,m) tile
#define NNZ_CAP 2048              // binomial(4096,0.25): mean 1024, sigma ~28 -> huge margin
#define TILES_PER_BLOCK 4
#define THREADS 256               // 8 warps: 2 warps per tile (each covers 64 f as float2)

// Compressed sparse metadata, rebuilt on-device every launch (deterministic,
// graph-capturable). Slot s = d*16 + a; entries are {val, c_offset_in_float2}.
__device__ int    g_soff[257];
__device__ float2 g_meta[NNZ_CAP];

// ---------------------------------------------------------------------------
// Prep: 1 block, 256 threads. Thread t owns slot (d=t>>4, a=t&15), scans c,
// prefix-sums counts, writes packed {val, coff2} entries.
// ---------------------------------------------------------------------------
__global__ void tp_prep_kernel(const float* __restrict__ cgc) {
    __shared__ int scan[256];
    int t = threadIdx.x;
    int d = t >> 4;
    int a = t & 15;

    float vals[AA];
    int   coffs[AA];
    int n = 0;
#pragma unroll
    for (int c = 0; c < AA; ++c) {
        float v = cgc[a * 256 + d * 16 + c];
        if (v != 0.0f) {
            vals[n]  = v;
            coffs[n] = c * (FF / 2);   // offset in float2 units into y tile
            ++n;
        }
    }

    scan[t] = n;
    __syncthreads();
    for (int off = 1; off < 256; off <<= 1) {
        int v = (t >= off) ? scan[t - off] : 0;
        __syncthreads();
        scan[t] += v;
        __syncthreads();
    }
    int base = scan[t] - n;  // exclusive
    g_soff[t] = base < NNZ_CAP ? base : NNZ_CAP;
    if (t == 255) g_soff[256] = scan[255] < NNZ_CAP ? scan[255] : NNZ_CAP;

    for (int i = 0; i < n; ++i) {
        int idx = base + i;
        if (idx < NNZ_CAP)
            g_meta[idx] = make_float2(vals[i], __int_as_float(coffs[i]));
    }
}

// ---------------------------------------------------------------------------
// Main: block = 256 threads = 8 warps = 4 (b,m) tiles, 2 warps per tile.
// Warp covers 64 of 128 f; lane holds a float2 f-slice.
//   out[d,f] = sum_a x[a,f] * ( sum_{c in list(d,a)} val * y[c,f] )
// x lives in registers (a is static in the unrolled loop); y in shared;
// metadata is a single warp-uniform LDS.64 broadcast per nnz.
// ---------------------------------------------------------------------------
__global__ __launch_bounds__(THREADS, 4) void tp_main_kernel(
    const float* __restrict__ x,
    const float* __restrict__ y,
    float* __restrict__ out)
{
    extern __shared__ float smem[];
    float*  ys    = smem;                                        // 4*2048 floats
    int*    soff  = (int*)(ys + TILES_PER_BLOCK * TILE_FLOATS);  // 257 (+3 pad)
    float2* smeta = (float2*)(soff + 260);                       // NNZ_CAP float2

    const int tid   = threadIdx.x;
    const int wid   = tid >> 5;
    const int lane  = tid & 31;
    const int tile  = wid >> 1;           // tile within block
    const int fhalf = wid & 1;            // which 64-f half this warp owns
    const int bm0   = blockIdx.x * TILES_PER_BLOCK;
    const int bm    = bm0 + tile;
    const int foff2 = fhalf * 32 + lane;  // float2 index within a 64-float2 row

    // Stage y for all 4 tiles (contiguous 8192 floats = 2048 float4)
    {
        const float4* yg  = (const float4*)(y + (size_t)bm0 * TILE_FLOATS);
        float4*       ys4 = (float4*)ys;
#pragma unroll
        for (int i = 0; i < (TILES_PER_BLOCK * TILE_FLOATS / 4); i += THREADS)
            ys4[i + tid] = yg[i + tid];
    }
    // Stage metadata
    for (int i = tid; i < 257; i += THREADS) soff[i] = g_soff[i];
#pragma unroll
    for (int i = 0; i < NNZ_CAP; i += THREADS) smeta[i + tid] = g_meta[i + tid];

    // x tile slice -> registers (static indices only)
    float2 x2[AA];
    {
        const float2* xg = (const float2*)(x + (size_t)bm * TILE_FLOATS);
#pragma unroll
        for (int a = 0; a < AA; ++a) x2[a] = xg[a * (FF / 2) + foff2];
    }
    __syncthreads();

    const float2* yw = (const float2*)(ys + tile * TILE_FLOATS);
    float2*       og = (float2*)(out + (size_t)bm * TILE_FLOATS);

#pragma unroll 1
    for (int d = 0; d < AA; ++d) {
        float ax = 0.f, ay = 0.f;
        int e_prev = soff[d << 4];
#pragma unroll
        for (int a = 0; a < AA; ++a) {
            int j = e_prev;
            int e = soff[(d << 4) + a + 1];
            e_prev = e;
            float s0x = 0.f, s0y = 0.f, s1x = 0.f, s1y = 0.f;
            // unroll-2 over the c-list (avg length ~4), dual accumulators
            while (j + 2 <= e) {
                float2 m0 = smeta[j];
                float2 m1 = smeta[j + 1];
                float2 y0 = yw[__float_as_int(m0.y) + foff2];
                float2 y1 = yw[__float_as_int(m1.y) + foff2];
                s0x = fmaf(m0.x, y0.x, s0x);
                s0y = fmaf(m0.x, y0.y, s0y);
                s1x = fmaf(m1.x, y1.x, s1x);
                s1y = fmaf(m1.x, y1.y, s1y);
                j += 2;
            }
            if (j < e) {
                float2 m0 = smeta[j];
                float2 y0 = yw[__float_as_int(m0.y) + foff2];
                s0x = fmaf(m0.x, y0.x, s0x);
                s0y = fmaf(m0.x, y0.y, s0y);
            }
            ax = fmaf(x2[a].x, s0x + s1x, ax);
            ay = fmaf(x2[a].y, s0y + s1y, ay);
        }
        og[(d << 6) + foff2] = make_float2(ax, ay);
    }
}

extern "C" void kernel_launch(void* const* d_in, const int* in_sizes, int n_in,
                              void* d_out, int out_size) {
    const float* x   = (const float*)d_in[0];
    const float* y   = (const float*)d_in[1];
    const float* cgc = (const float*)d_in[2];
    float* out = (float*)d_out;

    const int n_bm = in_sizes[0] / TILE_FLOATS;          // 4096
    const int grid = n_bm / TILES_PER_BLOCK;             // 1024

    const int smem_bytes =
        TILES_PER_BLOCK * TILE_FLOATS * 4                // y tiles: 32768
        + 260 * 4                                        // offsets (+pad)
        + NNZ_CAP * 8;                                   // packed meta

    cudaFuncSetAttribute(tp_main_kernel,
                         cudaFuncAttributeMaxDynamicSharedMemorySize,
                         smem_bytes);

    tp_prep_kernel<<<1, 256>>>(cgc);
    tp_main_kernel<<<grid, THREADS, smem_bytes>>>(x, y, out);
}

// round 5
// speedup vs baseline: 1.9625x; 1.3427x over previous
#include <cuda_runtime.h>
#include <cstdint>

// B=8, M=512, A=16, F=128. Dense register-resident contraction:
//   out[d,f] = sum_c ( sum_a cgc[a,d,c] * x[a,f] ) * y[c,f]
// computed as: per c: p[a] = x[a]*y[c] (f32x2), acc[d] += g[a,d,c]*p[a] dense.
// All f-vectors in registers (static indices); cgc duplicated {g,g} in smem,
// read via warp-uniform LDS.128 broadcasts.

#define AA 16
#define FF 128
#define TILE_FLOATS (AA * FF)    // 2048
#define TILES_PER_BLOCK 4
#define THREADS 256              // 8 warps: 2 warps/tile, 64 f per warp (float2/lane)

typedef unsigned long long ull;

__device__ __forceinline__ ull fma2(ull a, ull b, ull c) {
    ull d;
    asm("fma.rn.f32x2 %0, %1, %2, %3;" : "=l"(d) : "l"(a), "l"(b), "l"(c));
    return d;
}
__device__ __forceinline__ ull mul2(ull a, ull b) {
    ull d;
    asm("mul.rn.f32x2 %0, %1, %2;" : "=l"(d) : "l"(a), "l"(b));
    return d;
}

__global__ __launch_bounds__(THREADS, 2) void tp_dense_kernel(
    const float* __restrict__ x,
    const float* __restrict__ y,
    const float* __restrict__ cgc,
    float* __restrict__ out)
{
    // cgc re-laid-out as [c][d][a], each coefficient duplicated {g,g} -> 32 KB
    __shared__ ull gpair[AA * AA * AA];

    const int tid = threadIdx.x;

    // Stage + transpose + duplicate cgc (dest index i = c*256 + d*16 + a)
#pragma unroll
    for (int i = tid; i < AA * AA * AA; i += THREADS) {
        const int c = i >> 8;
        const int d = (i >> 4) & 15;
        const int a = i & 15;
        const unsigned int bits = __float_as_uint(cgc[a * 256 + d * 16 + c]);
        gpair[i] = ((ull)bits << 32) | bits;
    }

    const int wid  = tid >> 5;
    const int lane = tid & 31;
    const int tile = wid >> 1;
    const int fh   = wid & 1;
    const int bm   = blockIdx.x * TILES_PER_BLOCK + tile;
    const int fo   = fh * 32 + lane;     // float2 index within row, 0..63

    // x slice -> registers (16 coalesced LDG.64)
    const ull* xg = (const ull*)(x + (size_t)bm * TILE_FLOATS);
    ull x2[AA];
#pragma unroll
    for (int a = 0; a < AA; ++a) x2[a] = xg[a * (FF / 2) + fo];

    ull acc[AA];
#pragma unroll
    for (int d = 0; d < AA; ++d) acc[d] = 0ull;   // bit pattern of {+0.f,+0.f}

    __syncthreads();

    const ull* yg = (const ull*)(y + (size_t)bm * TILE_FLOATS);

#pragma unroll 1
    for (int c = 0; c < AA; ++c) {
        const ull yv = yg[c * (FF / 2) + fo];
        const ulonglong2* g2 = (const ulonglong2*)(gpair + c * 256);

        // split a into two halves of 8 to bound register pressure
#pragma unroll
        for (int h = 0; h < 2; ++h) {
            ull p[8];
#pragma unroll
            for (int a = 0; a < 8; ++a) p[a] = mul2(x2[h * 8 + a], yv);
#pragma unroll
            for (int d = 0; d < AA; ++d) {
                const ulonglong2* gd = g2 + d * 8 + h * 4;
                ull s = acc[d];
#pragma unroll
                for (int a4 = 0; a4 < 4; ++a4) {
                    const ulonglong2 gg = gd[a4];   // LDS.128 broadcast: 2 coeffs
                    s = fma2(gg.x, p[a4 * 2],     s);
                    s = fma2(gg.y, p[a4 * 2 + 1], s);
                }
                acc[d] = s;
            }
        }
    }

    ull* og = (ull*)(out + (size_t)bm * TILE_FLOATS);
#pragma unroll
    for (int d = 0; d < AA; ++d) og[d * (FF / 2) + fo] = acc[d];
}

extern "C" void kernel_launch(void* const* d_in, const int* in_sizes, int n_in,
                              void* d_out, int out_size) {
    const float* x   = (const float*)d_in[0];
    const float* y   = (const float*)d_in[1];
    const float* cgc = (const float*)d_in[2];
    float* out = (float*)d_out;

    const int n_bm = in_sizes[0] / TILE_FLOATS;          // 4096
    const int grid = n_bm / TILES_PER_BLOCK;             // 1024

    tp_dense_kernel<<<grid, THREADS>>>(x, y, cgc, out);
}

// round 6
// speedup vs baseline: 2.1647x; 1.1030x over previous
#include <cuda_runtime.h>
#include <cstdint>

// B=8, M=512, A=16, F=128. Dense register-resident contraction:
//   out[d,f] = sum_c ( sum_a cgc[a,d,c] * x[a,f] ) * y[c,f]
// One warp owns a full (b,m) tile: 128 f = 4 f/lane = 2 x f32x2 vectors.
// Coefficients duplicated {g,g} in smem, warp-uniform LDS.128 (2 pairs/load),
// amortized over 4 FFMA2 each.

#define AA 16
#define FF 128
#define TILE_FLOATS (AA * FF)    // 2048
#define WARPS_PER_BLOCK 4
#define THREADS 128

typedef unsigned long long ull;

__device__ __forceinline__ ull fma2(ull a, ull b, ull c) {
    ull d;
    asm("fma.rn.f32x2 %0, %1, %2, %3;" : "=l"(d) : "l"(a), "l"(b), "l"(c));
    return d;
}
__device__ __forceinline__ ull mul2(ull a, ull b) {
    ull d;
    asm("mul.rn.f32x2 %0, %1, %2;" : "=l"(d) : "l"(a), "l"(b));
    return d;
}

__global__ __launch_bounds__(THREADS, 2) void tp_dense_kernel(
    const float* __restrict__ x,
    const float* __restrict__ y,
    const float* __restrict__ cgc,
    float* __restrict__ out)
{
    // cgc re-laid-out as [c][d][a], each coefficient duplicated {g,g} -> 32 KB
    __shared__ __align__(16) ull gpair[AA * AA * AA];

    const int tid = threadIdx.x;

    // Stage + transpose + duplicate cgc (dest index i = c*256 + d*16 + a)
#pragma unroll
    for (int i = tid; i < AA * AA * AA; i += THREADS) {
        const int c = i >> 8;
        const int d = (i >> 4) & 15;
        const int a = i & 15;
        const unsigned int bits = __float_as_uint(cgc[a * 256 + d * 16 + c]);
        gpair[i] = ((ull)bits << 32) | bits;
    }

    const int wid  = tid >> 5;
    const int lane = tid & 31;
    const int bm   = blockIdx.x * WARPS_PER_BLOCK + wid;

    // x tile -> registers: lane holds float2 slots {lane, lane+32} of each 64-ull row
    const ull* xg = (const ull*)(x + (size_t)bm * TILE_FLOATS);
    ull x0[AA], x1[AA];
#pragma unroll
    for (int a = 0; a < AA; ++a) {
        x0[a] = xg[a * 64 + lane];
        x1[a] = xg[a * 64 + 32 + lane];
    }

    ull acc0[AA], acc1[AA];
#pragma unroll
    for (int d = 0; d < AA; ++d) { acc0[d] = 0ull; acc1[d] = 0ull; }

    __syncthreads();

    const ull* yg = (const ull*)(y + (size_t)bm * TILE_FLOATS);

#pragma unroll 1
    for (int c = 0; c < AA; ++c) {
        const ull yv0 = yg[c * 64 + lane];
        const ull yv1 = yg[c * 64 + 32 + lane];
        const ulonglong2* g2 = (const ulonglong2*)(gpair + c * 256);

        // a split into two halves of 8 to bound live p registers
#pragma unroll
        for (int h = 0; h < 2; ++h) {
            ull p0[8], p1[8];
#pragma unroll
            for (int a = 0; a < 8; ++a) {
                p0[a] = mul2(x0[h * 8 + a], yv0);
                p1[a] = mul2(x1[h * 8 + a], yv1);
            }
#pragma unroll
            for (int d = 0; d < AA; ++d) {
                const ulonglong2* gd = g2 + d * 8 + h * 4;
                ull s0 = acc0[d];
                ull s1 = acc1[d];
#pragma unroll
                for (int a4 = 0; a4 < 4; ++a4) {
                    const ulonglong2 gg = gd[a4];   // LDS.128: 2 dup'd coeffs
                    s0 = fma2(gg.x, p0[a4 * 2],     s0);
                    s1 = fma2(gg.x, p1[a4 * 2],     s1);
                    s0 = fma2(gg.y, p0[a4 * 2 + 1], s0);
                    s1 = fma2(gg.y, p1[a4 * 2 + 1], s1);
                }
                acc0[d] = s0;
                acc1[d] = s1;
            }
        }
    }

    ull* og = (ull*)(out + (size_t)bm * TILE_FLOATS);
#pragma unroll
    for (int d = 0; d < AA; ++d) {
        og[d * 64 + lane]      = acc0[d];
        og[d * 64 + 32 + lane] = acc1[d];
    }
}

extern "C" void kernel_launch(void* const* d_in, const int* in_sizes, int n_in,
                              void* d_out, int out_size) {
    const float* x   = (const float*)d_in[0];
    const float* y   = (const float*)d_in[1];
    const float* cgc = (const float*)d_in[2];
    float* out = (float*)d_out;

    const int n_bm = in_sizes[0] / TILE_FLOATS;          // 4096
    const int grid = n_bm / WARPS_PER_BLOCK;             // 1024

    tp_dense_kernel<<<grid, THREADS>>>(x, y, cgc, out);
}

// round 8
// speedup vs baseline: 2.4084x; 1.1125x over previous
#include <cuda_runtime.h>
#include <cstdint>

// B=8, M=512, A=16, F=128. Dense register-resident contraction:
//   out[d,f] = sum_c ( sum_a cgc[a,d,c] * x[a,f] ) * y[c,f]
// One warp owns a full (b,m) tile: 128 f = 2 x f32x2 vectors per lane.
// Per (c,d): t = sum_a g*x (register chain), then acc[d] += t*y.
// Coefficients duplicated {g,g} in smem, warp-uniform LDS.128 (2 coeffs/load),
// each feeding 4 FFMA2. No p[] scratch -> ~160 regs -> 3 blocks/SM.

#define AA 16
#define FF 128
#define TILE_FLOATS (AA * FF)    // 2048
#define WARPS_PER_BLOCK 4
#define THREADS 128

typedef unsigned long long ull;

__device__ __forceinline__ ull fma2(ull a, ull b, ull c) {
    ull d;
    asm("fma.rn.f32x2 %0, %1, %2, %3;" : "=l"(d) : "l"(a), "l"(b), "l"(c));
    return d;
}

__global__ __launch_bounds__(THREADS, 3) void tp_dense_kernel(
    const float* __restrict__ x,
    const float* __restrict__ y,
    const float* __restrict__ cgc,
    float* __restrict__ out)
{
    // cgc re-laid-out as [c][d][a], each coefficient duplicated {g,g} -> 32 KB
    __shared__ __align__(16) ull gpair[AA * AA * AA];

    const int tid = threadIdx.x;

    // Stage + transpose + duplicate cgc (dest index i = c*256 + d*16 + a)
#pragma unroll
    for (int i = tid; i < AA * AA * AA; i += THREADS) {
        const int c = i >> 8;
        const int d = (i >> 4) & 15;
        const int a = i & 15;
        const unsigned int bits = __float_as_uint(cgc[a * 256 + d * 16 + c]);
        gpair[i] = ((ull)bits << 32) | bits;
    }

    const int wid  = tid >> 5;
    const int lane = tid & 31;
    const int bm   = blockIdx.x * WARPS_PER_BLOCK + wid;

    // x tile -> registers: lane holds float2 slots {lane, lane+32} of each row
    const ull* xg = (const ull*)(x + (size_t)bm * TILE_FLOATS);
    ull x0[AA], x1[AA];
#pragma unroll
    for (int a = 0; a < AA; ++a) {
        x0[a] = xg[a * 64 + lane];
        x1[a] = xg[a * 64 + 32 + lane];
    }

    ull acc0[AA], acc1[AA];
#pragma unroll
    for (int d = 0; d < AA; ++d) { acc0[d] = 0ull; acc1[d] = 0ull; }

    __syncthreads();

    const ull* yg = (const ull*)(y + (size_t)bm * TILE_FLOATS);

#pragma unroll 1
    for (int c = 0; c < AA; ++c) {
        const ull yv0 = yg[c * 64 + lane];
        const ull yv1 = yg[c * 64 + 32 + lane];
        const ulonglong2* g2 = (const ulonglong2*)(gpair + c * 256);

#pragma unroll
        for (int d = 0; d < AA; ++d) {
            const ulonglong2* gd = g2 + d * 8;
            ull t0 = 0ull, t1 = 0ull;
#pragma unroll
            for (int a2 = 0; a2 < 8; ++a2) {
                const ulonglong2 gg = gd[a2];   // LDS.128: 2 dup'd coeffs
                t0 = fma2(gg.x, x0[a2 * 2],     t0);
                t1 = fma2(gg.x, x1[a2 * 2],     t1);
                t0 = fma2(gg.y, x0[a2 * 2 + 1], t0);
                t1 = fma2(gg.y, x1[a2 * 2 + 1], t1);
            }
            acc0[d] = fma2(t0, yv0, acc0[d]);
            acc1[d] = fma2(t1, yv1, acc1[d]);
        }
    }

    ull* og = (ull*)(out + (size_t)bm * TILE_FLOATS);
#pragma unroll
    for (int d = 0; d < AA; ++d) {
        og[d * 64 + lane]      = acc0[d];
        og[d * 64 + 32 + lane] = acc1[d];
    }
}

extern "C" void kernel_launch(void* const* d_in, const int* in_sizes, int n_in,
                              void* d_out, int out_size) {
    const float* x   = (const float*)d_in[0];
    const float* y   = (const float*)d_in[1];
    const float* cgc = (const float*)d_in[2];
    float* out = (float*)d_out;

    const int n_bm = in_sizes[0] / TILE_FLOATS;          // 4096
    const int grid = n_bm / WARPS_PER_BLOCK;             // 1024

    tp_dense_kernel<<<grid, THREADS>>>(x, y, cgc, out);
}